// round 1
// baseline (speedup 1.0000x reference)
#include <cuda_runtime.h>

// ---------------------------------------------------------------------------
// TransIFF encoder: 2-layer deformable-box-attention transformer encoder.
// B=1, H=W=128 -> L=16384 tokens, D=256, NH=8, HD=32, K2=25, DFF=1024.
// Round 1: correct fp32 implementation; tiled SGEMM + fused epilogues,
// warp-per-(token,head) bilinear sampler, fused residual+LayerNorm.
// ---------------------------------------------------------------------------

namespace {
constexpr int L    = 16384;
constexpr int D    = 256;
constexpr int NH   = 8;
constexpr int HD   = 32;
constexpr int K2   = 25;
constexpr int DFF  = 1024;
constexpr int HDIM = 128;
constexpr int WDIM = 128;
constexpr float EPS = 1e-5f;
}

// ------------------------- scratch (device globals) -----------------------
__device__ float g_X[L * D];          // token-major activations
__device__ float g_P[L * D];          // token-major positional
__device__ float g_Q[L * D];          // q = x + p
__device__ float g_VAL[L * D];        // value projection
__device__ float g_OUT[L * D];        // sampled attention output
__device__ float g_TMP[L * D];        // gemm output before residual+LN
__device__ float g_FF[L * DFF];       // FFN hidden
__device__ float g_AW[L * NH * K2];   // attention weights (softmaxed in place)
__device__ float g_OFF[L * NH * 4];   // box offsets

// ------------------------- transpose (D, L) -> (L, D) ---------------------
__global__ void transpose_kernel(const float* __restrict__ S, float* __restrict__ O) {
    __shared__ float t[32][33];
    int bx = blockIdx.x * 32;  // over L
    int by = blockIdx.y * 32;  // over D
    int tx = threadIdx.x, ty = threadIdx.y;  // 32 x 8
#pragma unroll
    for (int j = 0; j < 32; j += 8)
        t[ty + j][tx] = S[(size_t)(by + ty + j) * L + bx + tx];
    __syncthreads();
#pragma unroll
    for (int j = 0; j < 32; j += 8)
        O[(size_t)(bx + ty + j) * D + by + tx] = t[tx][ty + j];
}

// ------------------------- elementwise add --------------------------------
__global__ void add_kernel(const float* __restrict__ a, const float* __restrict__ b,
                           float* __restrict__ o, int n) {
    int i = blockIdx.x * blockDim.x + threadIdx.x;
    if (i < n) o[i] = a[i] + b[i];
}

// ------------------------- tiled SGEMM with fused epilogue ----------------
// C[M,N] = A[M,K] @ B[K,N] (+bias) (+relu).  A,B,C row-major.
// BM=BN=64, BK=16, TM=TN=4, 256 threads per block.
template <int EPI>  // 0 = none, 1 = +bias, 2 = +bias+relu
__global__ void sgemm_kernel(const float* __restrict__ A, const float* __restrict__ B,
                             const float* __restrict__ bias, float* __restrict__ C,
                             int M, int N, int K) {
    constexpr int BM = 64, BN = 64, BK = 16, TM = 4, TN = 4;
    __shared__ float As[BK][BM];
    __shared__ float Bs[BK][BN];

    int tid = threadIdx.x;
    int bm  = blockIdx.y * BM;
    int bn  = blockIdx.x * BN;
    int tx  = tid % (BN / TN);  // 0..15
    int ty  = tid / (BN / TN);  // 0..15

    float acc[TM][TN] = {};

    for (int k0 = 0; k0 < K; k0 += BK) {
        // A tile: BM x BK -> As[k][m]
#pragma unroll
        for (int i = tid; i < BM * BK; i += 256) {
            int m = i / BK, k = i % BK;
            As[k][m] = A[(size_t)(bm + m) * K + k0 + k];
        }
        // B tile: BK x BN -> Bs[k][n]
#pragma unroll
        for (int i = tid; i < BK * BN; i += 256) {
            int k = i / BN, n = i % BN;
            int gn = bn + n;
            Bs[k][n] = (gn < N) ? B[(size_t)(k0 + k) * N + gn] : 0.f;
        }
        __syncthreads();
#pragma unroll
        for (int k = 0; k < BK; k++) {
            float a[TM], b[TN];
#pragma unroll
            for (int i = 0; i < TM; i++) a[i] = As[k][ty * TM + i];
#pragma unroll
            for (int j = 0; j < TN; j++) b[j] = Bs[k][tx * TN + j];
#pragma unroll
            for (int i = 0; i < TM; i++)
#pragma unroll
                for (int j = 0; j < TN; j++)
                    acc[i][j] = fmaf(a[i], b[j], acc[i][j]);
        }
        __syncthreads();
    }

#pragma unroll
    for (int i = 0; i < TM; i++) {
        int gm = bm + ty * TM + i;
#pragma unroll
        for (int j = 0; j < TN; j++) {
            int gn = bn + tx * TN + j;
            if (gn >= N) continue;
            float v = acc[i][j];
            if (EPI >= 1) v += bias[gn];
            if (EPI == 2) v = fmaxf(v, 0.f);
            C[(size_t)gm * N + gn] = v;
        }
    }
}

// ------------------------- softmax over K2=25 per (l, h) ------------------
__global__ void softmax25_kernel(float* __restrict__ AW) {
    int g = blockIdx.x * blockDim.x + threadIdx.x;
    if (g >= L * NH) return;
    float* p = AW + (size_t)(g / NH) * (NH * K2) + (size_t)(g % NH) * K2;
    float v[K2];
    float mx = -1e30f;
#pragma unroll
    for (int k = 0; k < K2; k++) { v[k] = p[k]; mx = fmaxf(mx, v[k]); }
    float s = 0.f;
#pragma unroll
    for (int k = 0; k < K2; k++) { v[k] = __expf(v[k] - mx); s += v[k]; }
    float inv = 1.f / s;
#pragma unroll
    for (int k = 0; k < K2; k++) p[k] = v[k] * inv;
}

// ------------------------- deformable box sampling ------------------------
// One block per token l; 8 warps = 8 heads. Lane = channel within head.
__global__ void box_sample_kernel(const float* __restrict__ VAL,   // L x 256
                                  const float* __restrict__ AW,    // L x 200 (softmaxed)
                                  const float* __restrict__ OFF,   // L x 32
                                  float* __restrict__ OUT) {       // L x 256
    int l    = blockIdx.x;
    int h    = threadIdx.x >> 5;
    int lane = threadIdx.x & 31;

    int ix = l % WDIM, iy = l / WDIM;
    float cx = (ix + 0.5f) * (1.0f / WDIM);
    float cy = (iy + 0.5f) * (1.0f / HDIM);

    const float* off = OFF + (size_t)l * (NH * 4) + h * 4;
    const float scl = 0.025f * 0.125f;  // refb_wh / 8
    float bx = cx + off[0] * scl;
    float by = cy + off[1] * scl;
    float bw = 0.025f + off[2] * scl;
    float bh = 0.025f + off[3] * scl;

    const float* aw    = AW + (size_t)l * (NH * K2) + h * K2;
    const float* vbase = VAL + h * HD + lane;

    float acc = 0.f;
    for (int k = 0; k < K2; k++) {
        int kx = k % 5, ky = k / 5;
        float gx = -0.5f + 0.25f * kx;
        float gy = -0.5f + 0.25f * ky;
        float px = (bx + bw * gx) * (float)WDIM - 0.5f;
        float py = (by + bh * gy) * (float)HDIM - 0.5f;
        float x0 = floorf(px), y0 = floorf(py);
        float a  = aw[k];
#pragma unroll
        for (int dx = 0; dx < 2; dx++) {
#pragma unroll
            for (int dy = 0; dy < 2; dy++) {
                float xi = x0 + dx, yi = y0 + dy;
                if (xi < 0.f || xi >= (float)WDIM || yi < 0.f || yi >= (float)HDIM) continue;
                float w = (1.f - fabsf(px - xi)) * (1.f - fabsf(py - yi));
                int idx = (int)yi * WDIM + (int)xi;
                acc = fmaf(a * w, vbase[(size_t)idx * D], acc);
            }
        }
    }
    OUT[(size_t)l * D + h * HD + lane] = acc;
}

// ------------------------- fused residual + LayerNorm ---------------------
// One warp per row of 256. Out = LN(Xin + Add) * gamma + beta.
__global__ void ln_residual_kernel(const float* __restrict__ Xin,
                                   const float* __restrict__ Add,
                                   const float* __restrict__ gamma,
                                   const float* __restrict__ beta,
                                   float* __restrict__ Out) {
    int row  = blockIdx.x * (blockDim.x >> 5) + (threadIdx.x >> 5);
    int lane = threadIdx.x & 31;
    if (row >= L) return;
    const float* xr = Xin + (size_t)row * D;
    const float* ar = Add + (size_t)row * D;
    float v[D / 32];
    float s = 0.f;
#pragma unroll
    for (int i = 0; i < D / 32; i++) {
        int c = lane + 32 * i;
        v[i] = xr[c] + ar[c];
        s += v[i];
    }
#pragma unroll
    for (int o = 16; o; o >>= 1) s += __shfl_xor_sync(0xFFFFFFFFu, s, o);
    float m = s * (1.f / D);
    float vs = 0.f;
#pragma unroll
    for (int i = 0; i < D / 32; i++) {
        float d = v[i] - m;
        vs += d * d;
    }
#pragma unroll
    for (int o = 16; o; o >>= 1) vs += __shfl_xor_sync(0xFFFFFFFFu, vs, o);
    float rstd = rsqrtf(vs * (1.f / D) + EPS);
    float* orow = Out + (size_t)row * D;
#pragma unroll
    for (int i = 0; i < D / 32; i++) {
        int c = lane + 32 * i;
        orow[c] = (v[i] - m) * rstd * gamma[c] + beta[c];
    }
}

// ------------------------- host-side launcher ------------------------------
template <int EPI>
static void launch_gemm(const float* A, const float* B, const float* bias,
                        float* C, int M, int N, int K) {
    dim3 grid((N + 63) / 64, (M + 63) / 64);
    sgemm_kernel<EPI><<<grid, 256>>>(A, B, bias, C, M, N, K);
}

extern "C" void kernel_launch(void* const* d_in, const int* in_sizes, int n_in,
                              void* d_out, int out_size) {
    const float* src   = (const float*)d_in[0];
    const float* pos   = (const float*)d_in[1];
    const float* Wv    = (const float*)d_in[2];
    const float* bv    = (const float*)d_in[3];
    const float* Wbox  = (const float*)d_in[4];
    const float* bbox  = (const float*)d_in[5];
    const float* Wattn = (const float*)d_in[6];
    const float* battn = (const float*)d_in[7];
    const float* Wo    = (const float*)d_in[8];
    const float* bo    = (const float*)d_in[9];
    const float* W1    = (const float*)d_in[10];
    const float* b1    = (const float*)d_in[11];
    const float* W2    = (const float*)d_in[12];
    const float* b2    = (const float*)d_in[13];
    const float* ln1_g = (const float*)d_in[14];
    const float* ln1_b = (const float*)d_in[15];
    const float* ln2_g = (const float*)d_in[16];
    const float* ln2_b = (const float*)d_in[17];

    float *X, *P, *Q, *VAL, *OUT, *TMP, *FF, *AW, *OFF;
    cudaGetSymbolAddress((void**)&X,   g_X);
    cudaGetSymbolAddress((void**)&P,   g_P);
    cudaGetSymbolAddress((void**)&Q,   g_Q);
    cudaGetSymbolAddress((void**)&VAL, g_VAL);
    cudaGetSymbolAddress((void**)&OUT, g_OUT);
    cudaGetSymbolAddress((void**)&TMP, g_TMP);
    cudaGetSymbolAddress((void**)&FF,  g_FF);
    cudaGetSymbolAddress((void**)&AW,  g_AW);
    cudaGetSymbolAddress((void**)&OFF, g_OFF);

    // src/pos: (D, L) -> token-major (L, D)
    {
        dim3 tb(32, 8);
        dim3 tg(L / 32, D / 32);
        transpose_kernel<<<tg, tb>>>(src, X);
        transpose_kernel<<<tg, tb>>>(pos, P);
    }

    for (int i = 0; i < 2; i++) {
        const float* Wv_i    = Wv    + (size_t)i * D * D;
        const float* bv_i    = bv    + (size_t)i * D;
        const float* Wbox_i  = Wbox  + (size_t)i * D * (NH * 4);
        const float* bbox_i  = bbox  + (size_t)i * (NH * 4);
        const float* Wattn_i = Wattn + (size_t)i * D * (NH * K2);
        const float* battn_i = battn + (size_t)i * (NH * K2);
        const float* Wo_i    = Wo    + (size_t)i * D * D;
        const float* bo_i    = bo    + (size_t)i * D;
        const float* W1_i    = W1    + (size_t)i * D * DFF;
        const float* b1_i    = b1    + (size_t)i * DFF;
        const float* W2_i    = W2    + (size_t)i * DFF * D;
        const float* b2_i    = b2    + (size_t)i * D;
        const float* ln1g_i  = ln1_g + (size_t)i * D;
        const float* ln1b_i  = ln1_b + (size_t)i * D;
        const float* ln2g_i  = ln2_g + (size_t)i * D;
        const float* ln2b_i  = ln2_b + (size_t)i * D;

        // q = x + p
        add_kernel<<<(L * D + 255) / 256, 256>>>(X, P, Q, L * D);

        // val = x @ Wv + bv
        launch_gemm<1>(X, Wv_i, bv_i, VAL, L, D, D);
        // attn logits = q @ Wattn + battn, then softmax over 25
        launch_gemm<1>(Q, Wattn_i, battn_i, AW, L, NH * K2, D);
        softmax25_kernel<<<(L * NH + 255) / 256, 256>>>(AW);
        // off = q @ Wbox + bbox
        launch_gemm<1>(Q, Wbox_i, bbox_i, OFF, L, NH * 4, D);

        // deformable box sampling -> OUT
        box_sample_kernel<<<L, NH * 32>>>(VAL, AW, OFF, OUT);

        // a = OUT @ Wo + bo ; x = LN(x + a)
        launch_gemm<1>(OUT, Wo_i, bo_i, TMP, L, D, D);
        ln_residual_kernel<<<L / 8, 256>>>(X, TMP, ln1g_i, ln1b_i, X);

        // ff = relu(x @ W1 + b1) @ W2 + b2 ; x = LN(x + ff)
        launch_gemm<2>(X, W1_i, b1_i, FF, L, DFF, D);
        launch_gemm<1>(FF, W2_i, b2_i, TMP, L, D, DFF);
        float* lnout = (i == 1) ? (float*)d_out : X;
        ln_residual_kernel<<<L / 8, 256>>>(X, TMP, ln2g_i, ln2b_i, lnout);
    }
}

// round 2
// speedup vs baseline: 2.6339x; 2.6339x over previous
#include <cuda_runtime.h>
#include <cstdint>

// ---------------------------------------------------------------------------
// TransIFF encoder: 2-layer deformable-box-attention transformer encoder.
// B=1, H=W=128 -> L=16384 tokens, D=256, NH=8, HD=32, K2=25, DFF=1024.
// Round 2: TF32 tensor-core GEMMs (mma.sync m16n8k8) for all big matmuls.
// ---------------------------------------------------------------------------

namespace {
constexpr int L    = 16384;
constexpr int D    = 256;
constexpr int NH   = 8;
constexpr int HD   = 32;
constexpr int K2   = 25;
constexpr int DFF  = 1024;
constexpr int HDIM = 128;
constexpr int WDIM = 128;
constexpr float EPS = 1e-5f;
}

// ------------------------- scratch (device globals) -----------------------
__device__ float g_X[L * D];
__device__ float g_P[L * D];
__device__ float g_Q[L * D];
__device__ float g_VAL[L * D];
__device__ float g_OUT[L * D];
__device__ float g_TMP[L * D];
__device__ float g_FF[L * DFF];
__device__ float g_AW[L * NH * K2];
__device__ float g_OFF[L * NH * 4];

// ------------------------- helpers ----------------------------------------
__device__ __forceinline__ uint32_t f2tf32(float x) {
    uint32_t r;
    asm("cvt.rna.tf32.f32 %0, %1;" : "=r"(r) : "f"(x));
    return r;
}

__device__ __forceinline__ void mma_tf32(float d[4], const uint32_t a[4], const uint32_t b[2]) {
    asm volatile(
        "mma.sync.aligned.m16n8k8.row.col.f32.tf32.tf32.f32 "
        "{%0,%1,%2,%3}, {%4,%5,%6,%7}, {%8,%9}, {%0,%1,%2,%3};\n"
        : "+f"(d[0]), "+f"(d[1]), "+f"(d[2]), "+f"(d[3])
        : "r"(a[0]), "r"(a[1]), "r"(a[2]), "r"(a[3]), "r"(b[0]), "r"(b[1]));
}

// ------------------------- TF32 tensor-core GEMM ---------------------------
// C[M,N] = A[M,K] @ B[K,N] (+bias)(+relu). Row-major. M%128==0, K%32==0,
// N arbitrary (predicated). Block: 128x128x32 tile, 256 threads (8 warps),
// warps arranged 2(m) x 4(n); each warp computes 64x32 via 16 m16n8k8 mmas.
template <int EPI>  // 0 = none, 1 = +bias, 2 = +bias+relu
__global__ void __launch_bounds__(256, 2)
mma_gemm_kernel(const float* __restrict__ A, const float* __restrict__ B,
                const float* __restrict__ bias, float* __restrict__ C,
                int M, int N, int K) {
    constexpr int BM = 128, BN = 128, BK = 32;
    constexpr int ASTR = BK + 4;   // 36 words/row  -> conflict-free frag loads
    constexpr int BSTR = BN + 4;   // 132 words/row -> conflict-free frag loads
    __shared__ uint32_t As[BM * ASTR];
    __shared__ uint32_t Bs[BK * BSTR];

    const int tid  = threadIdx.x;
    const int warp = tid >> 5;
    const int lane = tid & 31;
    const int g    = lane >> 2;   // groupID (0..7)
    const int t    = lane & 3;    // threadID_in_group (0..3)
    const int wm   = warp & 1;    // 2 warps along M (64 rows each)
    const int wn   = warp >> 1;   // 4 warps along N (32 cols each)
    const int bm   = blockIdx.y * BM;
    const int bn   = blockIdx.x * BN;

    float acc[4][4][4] = {};      // [mt][nt][c0..c3]

    for (int k0 = 0; k0 < K; k0 += BK) {
        // ---- A tile: BM x BK floats = 1024 float4; 4 per thread
#pragma unroll
        for (int it = 0; it < 4; it++) {
            int i = tid + it * 256;
            int r = i >> 3;
            int c = (i & 7) * 4;
            float4 v = *(const float4*)(A + (size_t)(bm + r) * K + k0 + c);
            uint32_t* dst = As + r * ASTR + c;
            dst[0] = f2tf32(v.x); dst[1] = f2tf32(v.y);
            dst[2] = f2tf32(v.z); dst[3] = f2tf32(v.w);
        }
        // ---- B tile: BK x BN floats = 1024 float4; 4 per thread (N-guarded)
#pragma unroll
        for (int it = 0; it < 4; it++) {
            int i = tid + it * 256;
            int r = i >> 5;
            int c = (i & 31) * 4;
            int gn = bn + c;
            const float* bp = B + (size_t)(k0 + r) * N;
            float4 v = make_float4(0.f, 0.f, 0.f, 0.f);
            if (gn + 3 < N) {
                v = *(const float4*)(bp + gn);
            } else {
                if (gn     < N) v.x = bp[gn];
                if (gn + 1 < N) v.y = bp[gn + 1];
                if (gn + 2 < N) v.z = bp[gn + 2];
            }
            uint32_t* dst = Bs + r * BSTR + c;
            dst[0] = f2tf32(v.x); dst[1] = f2tf32(v.y);
            dst[2] = f2tf32(v.z); dst[3] = f2tf32(v.w);
        }
        __syncthreads();

#pragma unroll
        for (int k8 = 0; k8 < BK; k8 += 8) {
            uint32_t af[4][4], bf[4][2];
#pragma unroll
            for (int mt = 0; mt < 4; mt++) {
                int row = wm * 64 + mt * 16 + g;
                const uint32_t* a0 = As + row * ASTR + k8;
                const uint32_t* a8 = a0 + 8 * ASTR;
                af[mt][0] = a0[t];
                af[mt][1] = a8[t];
                af[mt][2] = a0[t + 4];
                af[mt][3] = a8[t + 4];
            }
#pragma unroll
            for (int nt = 0; nt < 4; nt++) {
                int col = wn * 32 + nt * 8 + g;
                bf[nt][0] = Bs[(k8 + t) * BSTR + col];
                bf[nt][1] = Bs[(k8 + t + 4) * BSTR + col];
            }
#pragma unroll
            for (int mt = 0; mt < 4; mt++)
#pragma unroll
                for (int nt = 0; nt < 4; nt++)
                    mma_tf32(acc[mt][nt], af[mt], bf[nt]);
        }
        __syncthreads();
    }

    // ---- epilogue: bias / relu, float2 stores ----
#pragma unroll
    for (int mt = 0; mt < 4; mt++) {
        int r0 = bm + wm * 64 + mt * 16 + g;
#pragma unroll
        for (int nt = 0; nt < 4; nt++) {
            int col = bn + wn * 32 + nt * 8 + 2 * t;
            if (col >= N) continue;   // N is always even here
            float b0 = 0.f, b1 = 0.f;
            if (EPI >= 1) { b0 = bias[col]; b1 = bias[col + 1]; }
            float v0 = acc[mt][nt][0] + b0;
            float v1 = acc[mt][nt][1] + b1;
            float v2 = acc[mt][nt][2] + b0;
            float v3 = acc[mt][nt][3] + b1;
            if (EPI == 2) {
                v0 = fmaxf(v0, 0.f); v1 = fmaxf(v1, 0.f);
                v2 = fmaxf(v2, 0.f); v3 = fmaxf(v3, 0.f);
            }
            *(float2*)(C + (size_t)r0 * N + col)       = make_float2(v0, v1);
            *(float2*)(C + (size_t)(r0 + 8) * N + col) = make_float2(v2, v3);
        }
    }
}

// ------------------------- transpose (D, L) -> (L, D) ---------------------
__global__ void transpose_kernel(const float* __restrict__ S, float* __restrict__ O) {
    __shared__ float tbuf[32][33];
    int bx = blockIdx.x * 32;
    int by = blockIdx.y * 32;
    int tx = threadIdx.x, ty = threadIdx.y;
#pragma unroll
    for (int j = 0; j < 32; j += 8)
        tbuf[ty + j][tx] = S[(size_t)(by + ty + j) * L + bx + tx];
    __syncthreads();
#pragma unroll
    for (int j = 0; j < 32; j += 8)
        O[(size_t)(bx + ty + j) * D + by + tx] = tbuf[tx][ty + j];
}

// ------------------------- elementwise add --------------------------------
__global__ void add_kernel(const float* __restrict__ a, const float* __restrict__ b,
                           float* __restrict__ o, int n) {
    int i = blockIdx.x * blockDim.x + threadIdx.x;
    if (i < n) o[i] = a[i] + b[i];
}

// ------------------------- SIMT SGEMM (small-N fallback, Wbox) ------------
template <int EPI>
__global__ void sgemm_kernel(const float* __restrict__ A, const float* __restrict__ B,
                             const float* __restrict__ bias, float* __restrict__ C,
                             int M, int N, int K) {
    constexpr int BM = 64, BN = 64, BK = 16, TM = 4, TN = 4;
    __shared__ float As[BK][BM];
    __shared__ float Bs[BK][BN];

    int tid = threadIdx.x;
    int bm  = blockIdx.y * BM;
    int bn  = blockIdx.x * BN;
    int tx  = tid % (BN / TN);
    int ty  = tid / (BN / TN);

    float acc[TM][TN] = {};

    for (int k0 = 0; k0 < K; k0 += BK) {
#pragma unroll
        for (int i = tid; i < BM * BK; i += 256) {
            int m = i / BK, k = i % BK;
            As[k][m] = A[(size_t)(bm + m) * K + k0 + k];
        }
#pragma unroll
        for (int i = tid; i < BK * BN; i += 256) {
            int k = i / BN, n = i % BN;
            int gn = bn + n;
            Bs[k][n] = (gn < N) ? B[(size_t)(k0 + k) * N + gn] : 0.f;
        }
        __syncthreads();
#pragma unroll
        for (int k = 0; k < BK; k++) {
            float a[TM], b[TN];
#pragma unroll
            for (int i = 0; i < TM; i++) a[i] = As[k][ty * TM + i];
#pragma unroll
            for (int j = 0; j < TN; j++) b[j] = Bs[k][tx * TN + j];
#pragma unroll
            for (int i = 0; i < TM; i++)
#pragma unroll
                for (int j = 0; j < TN; j++)
                    acc[i][j] = fmaf(a[i], b[j], acc[i][j]);
        }
        __syncthreads();
    }

#pragma unroll
    for (int i = 0; i < TM; i++) {
        int gm = bm + ty * TM + i;
#pragma unroll
        for (int j = 0; j < TN; j++) {
            int gn = bn + tx * TN + j;
            if (gn >= N) continue;
            float v = acc[i][j];
            if (EPI >= 1) v += bias[gn];
            if (EPI == 2) v = fmaxf(v, 0.f);
            C[(size_t)gm * N + gn] = v;
        }
    }
}

// ------------------------- softmax over K2=25 per (l, h) ------------------
__global__ void softmax25_kernel(float* __restrict__ AW) {
    int g = blockIdx.x * blockDim.x + threadIdx.x;
    if (g >= L * NH) return;
    float* p = AW + (size_t)(g / NH) * (NH * K2) + (size_t)(g % NH) * K2;
    float v[K2];
    float mx = -1e30f;
#pragma unroll
    for (int k = 0; k < K2; k++) { v[k] = p[k]; mx = fmaxf(mx, v[k]); }
    float s = 0.f;
#pragma unroll
    for (int k = 0; k < K2; k++) { v[k] = __expf(v[k] - mx); s += v[k]; }
    float inv = 1.f / s;
#pragma unroll
    for (int k = 0; k < K2; k++) p[k] = v[k] * inv;
}

// ------------------------- deformable box sampling ------------------------
__global__ void box_sample_kernel(const float* __restrict__ VAL,
                                  const float* __restrict__ AW,
                                  const float* __restrict__ OFF,
                                  float* __restrict__ OUT) {
    int l    = blockIdx.x;
    int h    = threadIdx.x >> 5;
    int lane = threadIdx.x & 31;

    int ix = l % WDIM, iy = l / WDIM;
    float cx = (ix + 0.5f) * (1.0f / WDIM);
    float cy = (iy + 0.5f) * (1.0f / HDIM);

    const float* off = OFF + (size_t)l * (NH * 4) + h * 4;
    const float scl = 0.025f * 0.125f;
    float bx = cx + off[0] * scl;
    float by = cy + off[1] * scl;
    float bw = 0.025f + off[2] * scl;
    float bh = 0.025f + off[3] * scl;

    const float* aw    = AW + (size_t)l * (NH * K2) + h * K2;
    const float* vbase = VAL + h * HD + lane;

    float acc = 0.f;
    for (int k = 0; k < K2; k++) {
        int kx = k % 5, ky = k / 5;
        float gx = -0.5f + 0.25f * kx;
        float gy = -0.5f + 0.25f * ky;
        float px = (bx + bw * gx) * (float)WDIM - 0.5f;
        float py = (by + bh * gy) * (float)HDIM - 0.5f;
        float x0 = floorf(px), y0 = floorf(py);
        float a  = aw[k];
#pragma unroll
        for (int dx = 0; dx < 2; dx++) {
#pragma unroll
            for (int dy = 0; dy < 2; dy++) {
                float xi = x0 + dx, yi = y0 + dy;
                if (xi < 0.f || xi >= (float)WDIM || yi < 0.f || yi >= (float)HDIM) continue;
                float w = (1.f - fabsf(px - xi)) * (1.f - fabsf(py - yi));
                int idx = (int)yi * WDIM + (int)xi;
                acc = fmaf(a * w, vbase[(size_t)idx * D], acc);
            }
        }
    }
    OUT[(size_t)l * D + h * HD + lane] = acc;
}

// ------------------------- fused residual + LayerNorm ---------------------
__global__ void ln_residual_kernel(const float* __restrict__ Xin,
                                   const float* __restrict__ Add,
                                   const float* __restrict__ gamma,
                                   const float* __restrict__ beta,
                                   float* __restrict__ Out) {
    int row  = blockIdx.x * (blockDim.x >> 5) + (threadIdx.x >> 5);
    int lane = threadIdx.x & 31;
    if (row >= L) return;
    const float* xr = Xin + (size_t)row * D;
    const float* ar = Add + (size_t)row * D;
    float v[D / 32];
    float s = 0.f;
#pragma unroll
    for (int i = 0; i < D / 32; i++) {
        int c = lane + 32 * i;
        v[i] = xr[c] + ar[c];
        s += v[i];
    }
#pragma unroll
    for (int o = 16; o; o >>= 1) s += __shfl_xor_sync(0xFFFFFFFFu, s, o);
    float m = s * (1.f / D);
    float vs = 0.f;
#pragma unroll
    for (int i = 0; i < D / 32; i++) {
        float d = v[i] - m;
        vs += d * d;
    }
#pragma unroll
    for (int o = 16; o; o >>= 1) vs += __shfl_xor_sync(0xFFFFFFFFu, vs, o);
    float rstd = rsqrtf(vs * (1.f / D) + EPS);
    float* orow = Out + (size_t)row * D;
#pragma unroll
    for (int i = 0; i < D / 32; i++) {
        int c = lane + 32 * i;
        orow[c] = (v[i] - m) * rstd * gamma[c] + beta[c];
    }
}

// ------------------------- host-side launchers -----------------------------
template <int EPI>
static void launch_mma_gemm(const float* A, const float* B, const float* bias,
                            float* C, int M, int N, int K) {
    dim3 grid((N + 127) / 128, M / 128);
    mma_gemm_kernel<EPI><<<grid, 256>>>(A, B, bias, C, M, N, K);
}

template <int EPI>
static void launch_sgemm(const float* A, const float* B, const float* bias,
                         float* C, int M, int N, int K) {
    dim3 grid((N + 63) / 64, (M + 63) / 64);
    sgemm_kernel<EPI><<<grid, 256>>>(A, B, bias, C, M, N, K);
}

extern "C" void kernel_launch(void* const* d_in, const int* in_sizes, int n_in,
                              void* d_out, int out_size) {
    const float* src   = (const float*)d_in[0];
    const float* pos   = (const float*)d_in[1];
    const float* Wv    = (const float*)d_in[2];
    const float* bv    = (const float*)d_in[3];
    const float* Wbox  = (const float*)d_in[4];
    const float* bbox  = (const float*)d_in[5];
    const float* Wattn = (const float*)d_in[6];
    const float* battn = (const float*)d_in[7];
    const float* Wo    = (const float*)d_in[8];
    const float* bo    = (const float*)d_in[9];
    const float* W1    = (const float*)d_in[10];
    const float* b1    = (const float*)d_in[11];
    const float* W2    = (const float*)d_in[12];
    const float* b2    = (const float*)d_in[13];
    const float* ln1_g = (const float*)d_in[14];
    const float* ln1_b = (const float*)d_in[15];
    const float* ln2_g = (const float*)d_in[16];
    const float* ln2_b = (const float*)d_in[17];

    float *X, *P, *Q, *VAL, *OUT, *TMP, *FF, *AW, *OFF;
    cudaGetSymbolAddress((void**)&X,   g_X);
    cudaGetSymbolAddress((void**)&P,   g_P);
    cudaGetSymbolAddress((void**)&Q,   g_Q);
    cudaGetSymbolAddress((void**)&VAL, g_VAL);
    cudaGetSymbolAddress((void**)&OUT, g_OUT);
    cudaGetSymbolAddress((void**)&TMP, g_TMP);
    cudaGetSymbolAddress((void**)&FF,  g_FF);
    cudaGetSymbolAddress((void**)&AW,  g_AW);
    cudaGetSymbolAddress((void**)&OFF, g_OFF);

    {
        dim3 tb(32, 8);
        dim3 tg(L / 32, D / 32);
        transpose_kernel<<<tg, tb>>>(src, X);
        transpose_kernel<<<tg, tb>>>(pos, P);
    }

    for (int i = 0; i < 2; i++) {
        const float* Wv_i    = Wv    + (size_t)i * D * D;
        const float* bv_i    = bv    + (size_t)i * D;
        const float* Wbox_i  = Wbox  + (size_t)i * D * (NH * 4);
        const float* bbox_i  = bbox  + (size_t)i * (NH * 4);
        const float* Wattn_i = Wattn + (size_t)i * D * (NH * K2);
        const float* battn_i = battn + (size_t)i * (NH * K2);
        const float* Wo_i    = Wo    + (size_t)i * D * D;
        const float* bo_i    = bo    + (size_t)i * D;
        const float* W1_i    = W1    + (size_t)i * D * DFF;
        const float* b1_i    = b1    + (size_t)i * DFF;
        const float* W2_i    = W2    + (size_t)i * DFF * D;
        const float* b2_i    = b2    + (size_t)i * D;
        const float* ln1g_i  = ln1_g + (size_t)i * D;
        const float* ln1b_i  = ln1_b + (size_t)i * D;
        const float* ln2g_i  = ln2_g + (size_t)i * D;
        const float* ln2b_i  = ln2_b + (size_t)i * D;

        add_kernel<<<(L * D + 255) / 256, 256>>>(X, P, Q, L * D);

        launch_mma_gemm<1>(X, Wv_i, bv_i, VAL, L, D, D);
        launch_mma_gemm<1>(Q, Wattn_i, battn_i, AW, L, NH * K2, D);
        softmax25_kernel<<<(L * NH + 255) / 256, 256>>>(AW);
        launch_sgemm<1>(Q, Wbox_i, bbox_i, OFF, L, NH * 4, D);

        box_sample_kernel<<<L, NH * 32>>>(VAL, AW, OFF, OUT);

        launch_mma_gemm<1>(OUT, Wo_i, bo_i, TMP, L, D, D);
        ln_residual_kernel<<<L / 8, 256>>>(X, TMP, ln1g_i, ln1b_i, X);

        launch_mma_gemm<2>(X, W1_i, b1_i, FF, L, DFF, D);
        launch_mma_gemm<1>(FF, W2_i, b2_i, TMP, L, D, DFF);
        float* lnout = (i == 1) ? (float*)d_out : X;
        ln_residual_kernel<<<L / 8, 256>>>(X, TMP, ln2g_i, ln2b_i, lnout);
    }
}

// round 3
// speedup vs baseline: 3.2469x; 1.2328x over previous
#include <cuda_runtime.h>
#include <cstdint>

// ---------------------------------------------------------------------------
// TransIFF encoder: 2-layer deformable-box-attention transformer encoder.
// B=1, H=W=128 -> L=16384 tokens, D=256, NH=8, HD=32, K2=25, DFF=1024.
// Round 3: cp.async double-buffered TF32 mma.sync GEMM (no cvt pass,
// HW-truncated tf32 inputs), all GEMMs on the tensor pipe.
// ---------------------------------------------------------------------------

namespace {
constexpr int L    = 16384;
constexpr int D    = 256;
constexpr int NH   = 8;
constexpr int HD   = 32;
constexpr int K2   = 25;
constexpr int DFF  = 1024;
constexpr int HDIM = 128;
constexpr int WDIM = 128;
constexpr float EPS = 1e-5f;

constexpr int BM = 128, BN = 128, BK = 32;
constexpr int ASTR = BK + 4;    // 36 words/row, 144B (16B-aligned rows)
constexpr int BSTR = BN + 4;    // 132 words/row, 528B (16B-aligned rows)
constexpr int ASIZE = BM * ASTR;         // words per stage
constexpr int BSIZE = BK * BSTR;         // words per stage
constexpr int SMEM_WORDS = 2 * (ASIZE + BSIZE);
constexpr int SMEM_BYTES = SMEM_WORDS * 4;   // 70656 B
}

// ------------------------- scratch (device globals) -----------------------
__device__ float g_X[L * D];
__device__ float g_P[L * D];
__device__ float g_Q[L * D];
__device__ float g_VAL[L * D];
__device__ float g_OUT[L * D];
__device__ float g_TMP[L * D];
__device__ float g_FF[L * DFF];
__device__ float g_AW[L * NH * K2];
__device__ float g_OFF[L * NH * 4];

// ------------------------- PTX helpers ------------------------------------
__device__ __forceinline__ uint32_t smem_u32(const void* p) {
    return (uint32_t)__cvta_generic_to_shared(p);
}

__device__ __forceinline__ void cp_async16(uint32_t saddr, const void* gaddr) {
    asm volatile("cp.async.ca.shared.global [%0], [%1], 16;\n"
                 :: "r"(saddr), "l"(gaddr));
}

__device__ __forceinline__ void cp_async16_zfill(uint32_t saddr, const void* gaddr, int bytes) {
    asm volatile("cp.async.ca.shared.global [%0], [%1], 16, %2;\n"
                 :: "r"(saddr), "l"(gaddr), "r"(bytes));
}

__device__ __forceinline__ void cp_commit() {
    asm volatile("cp.async.commit_group;\n");
}

template <int NG>
__device__ __forceinline__ void cp_wait() {
    asm volatile("cp.async.wait_group %0;\n" :: "n"(NG));
}

__device__ __forceinline__ void mma_tf32(float d[4], const uint32_t a[4], const uint32_t b[2]) {
    asm volatile(
        "mma.sync.aligned.m16n8k8.row.col.f32.tf32.tf32.f32 "
        "{%0,%1,%2,%3}, {%4,%5,%6,%7}, {%8,%9}, {%0,%1,%2,%3};\n"
        : "+f"(d[0]), "+f"(d[1]), "+f"(d[2]), "+f"(d[3])
        : "r"(a[0]), "r"(a[1]), "r"(a[2]), "r"(a[3]), "r"(b[0]), "r"(b[1]));
}

// ------------------------- TF32 tensor-core GEMM ---------------------------
// C[M,N] = A[M,K] @ B[K,N] (+bias)(+relu). Row-major. M%128==0, K%32==0,
// N arbitrary. 128x128x32 tiles, 256 threads (2x4 warps, 64x32 per warp),
// cp.async double-buffered. fp32 inputs fed to tf32 mma (HW truncation).
template <int EPI>  // 0 = none, 1 = +bias, 2 = +bias+relu
__global__ void __launch_bounds__(256, 2)
mma_gemm_kernel(const float* __restrict__ A, const float* __restrict__ B,
                const float* __restrict__ bias, float* __restrict__ C,
                int M, int N, int K) {
    extern __shared__ uint32_t smem[];
    uint32_t* As = smem;                  // 2 stages of ASIZE
    uint32_t* Bs = smem + 2 * ASIZE;      // 2 stages of BSIZE

    const int tid  = threadIdx.x;
    const int warp = tid >> 5;
    const int lane = tid & 31;
    const int g    = lane >> 2;
    const int t    = lane & 3;
    const int wm   = warp & 1;
    const int wn   = warp >> 1;
    const int bm   = blockIdx.y * BM;
    const int bn   = blockIdx.x * BN;

    // per-thread load coordinates (4 x 16B chunks each for A and B)
    const int ar = tid >> 3;            // 0..31 (A row step: +32 per chunk-iter)
    const int ac = (tid & 7) * 4;       // col in words
    const int br = tid >> 6;            // 0..3  (B row step: +4 per chunk-iter)
    const int bc = (tid & 63) * 4 >= BN ? ((tid & 63) * 4 - BN) : (tid & 63) * 4;
    // simpler: recompute below per-chunk

    auto load_tile = [&](int stage, int k0) {
        // A: 128x32 floats -> 1024 16B chunks, 4 per thread
        uint32_t abase = smem_u32(As + stage * ASIZE);
#pragma unroll
        for (int it = 0; it < 4; it++) {
            int id = tid + it * 256;
            int r = id >> 3;
            int c = (id & 7) * 4;
            cp_async16(abase + (r * ASTR + c) * 4,
                       A + (size_t)(bm + r) * K + k0 + c);
        }
        // B: 32x128 floats -> 1024 16B chunks, 4 per thread (N-guarded)
        uint32_t bbase = smem_u32(Bs + stage * BSIZE);
#pragma unroll
        for (int it = 0; it < 4; it++) {
            int id = tid + it * 256;
            int r = id >> 5;
            int c = (id & 31) * 4;
            int gn = bn + c;
            int rem = (N - gn) * 4;
            int bytes = rem >= 16 ? 16 : (rem > 0 ? rem : 0);
            const float* gp = B + (size_t)(k0 + r) * N + (gn < N ? gn : 0);
            cp_async16_zfill(bbase + (r * BSTR + c) * 4, gp, bytes);
        }
    };

    float acc[4][4][4] = {};

    const int nk = K / BK;
    load_tile(0, 0);
    cp_commit();

    for (int kt = 0; kt < nk; kt++) {
        const int cur = kt & 1;
        if (kt + 1 < nk) {
            load_tile(cur ^ 1, (kt + 1) * BK);
            cp_commit();
            cp_wait<1>();
        } else {
            cp_wait<0>();
        }
        __syncthreads();

        const uint32_t* Ac = As + cur * ASIZE;
        const uint32_t* Bc = Bs + cur * BSIZE;
#pragma unroll
        for (int k8 = 0; k8 < BK; k8 += 8) {
            uint32_t af[4][4], bf[4][2];
#pragma unroll
            for (int mt = 0; mt < 4; mt++) {
                int row = wm * 64 + mt * 16 + g;
                const uint32_t* a0 = Ac + row * ASTR + k8;
                const uint32_t* a8 = a0 + 8 * ASTR;
                af[mt][0] = a0[t];
                af[mt][1] = a8[t];
                af[mt][2] = a0[t + 4];
                af[mt][3] = a8[t + 4];
            }
#pragma unroll
            for (int nt = 0; nt < 4; nt++) {
                int col = wn * 32 + nt * 8 + g;
                bf[nt][0] = Bc[(k8 + t) * BSTR + col];
                bf[nt][1] = Bc[(k8 + t + 4) * BSTR + col];
            }
#pragma unroll
            for (int mt = 0; mt < 4; mt++)
#pragma unroll
                for (int nt = 0; nt < 4; nt++)
                    mma_tf32(acc[mt][nt], af[mt], bf[nt]);
        }
        __syncthreads();
    }

    // ---- epilogue ----
#pragma unroll
    for (int mt = 0; mt < 4; mt++) {
        int r0 = bm + wm * 64 + mt * 16 + g;
#pragma unroll
        for (int nt = 0; nt < 4; nt++) {
            int col = bn + wn * 32 + nt * 8 + 2 * t;
            if (col >= N) continue;   // N always even here
            float b0 = 0.f, b1 = 0.f;
            if (EPI >= 1) { b0 = bias[col]; b1 = bias[col + 1]; }
            float v0 = acc[mt][nt][0] + b0;
            float v1 = acc[mt][nt][1] + b1;
            float v2 = acc[mt][nt][2] + b0;
            float v3 = acc[mt][nt][3] + b1;
            if (EPI == 2) {
                v0 = fmaxf(v0, 0.f); v1 = fmaxf(v1, 0.f);
                v2 = fmaxf(v2, 0.f); v3 = fmaxf(v3, 0.f);
            }
            *(float2*)(C + (size_t)r0 * N + col)       = make_float2(v0, v1);
            *(float2*)(C + (size_t)(r0 + 8) * N + col) = make_float2(v2, v3);
        }
    }
}

// ------------------------- transpose (D, L) -> (L, D) ---------------------
__global__ void transpose_kernel(const float* __restrict__ S, float* __restrict__ O) {
    __shared__ float tbuf[32][33];
    int bx = blockIdx.x * 32;
    int by = blockIdx.y * 32;
    int tx = threadIdx.x, ty = threadIdx.y;
#pragma unroll
    for (int j = 0; j < 32; j += 8)
        tbuf[ty + j][tx] = S[(size_t)(by + ty + j) * L + bx + tx];
    __syncthreads();
#pragma unroll
    for (int j = 0; j < 32; j += 8)
        O[(size_t)(bx + ty + j) * D + by + tx] = tbuf[tx][ty + j];
}

// ------------------------- elementwise add --------------------------------
__global__ void add_kernel(const float* __restrict__ a, const float* __restrict__ b,
                           float* __restrict__ o, int n) {
    int i = blockIdx.x * blockDim.x + threadIdx.x;
    if (i < n) o[i] = a[i] + b[i];
}

// ------------------------- softmax over K2=25 per (l, h) ------------------
__global__ void softmax25_kernel(float* __restrict__ AW) {
    int g = blockIdx.x * blockDim.x + threadIdx.x;
    if (g >= L * NH) return;
    float* p = AW + (size_t)(g / NH) * (NH * K2) + (size_t)(g % NH) * K2;
    float v[K2];
    float mx = -1e30f;
#pragma unroll
    for (int k = 0; k < K2; k++) { v[k] = p[k]; mx = fmaxf(mx, v[k]); }
    float s = 0.f;
#pragma unroll
    for (int k = 0; k < K2; k++) { v[k] = __expf(v[k] - mx); s += v[k]; }
    float inv = 1.f / s;
#pragma unroll
    for (int k = 0; k < K2; k++) p[k] = v[k] * inv;
}

// ------------------------- deformable box sampling ------------------------
__global__ void box_sample_kernel(const float* __restrict__ VAL,
                                  const float* __restrict__ AW,
                                  const float* __restrict__ OFF,
                                  float* __restrict__ OUT) {
    int l    = blockIdx.x;
    int h    = threadIdx.x >> 5;
    int lane = threadIdx.x & 31;

    int ix = l % WDIM, iy = l / WDIM;
    float cx = (ix + 0.5f) * (1.0f / WDIM);
    float cy = (iy + 0.5f) * (1.0f / HDIM);

    const float* off = OFF + (size_t)l * (NH * 4) + h * 4;
    const float scl = 0.025f * 0.125f;
    float bx = cx + off[0] * scl;
    float by = cy + off[1] * scl;
    float bw = 0.025f + off[2] * scl;
    float bh = 0.025f + off[3] * scl;

    const float* aw    = AW + (size_t)l * (NH * K2) + h * K2;
    const float* vbase = VAL + h * HD + lane;

    float acc = 0.f;
    for (int k = 0; k < K2; k++) {
        int kx = k % 5, ky = k / 5;
        float gx = -0.5f + 0.25f * kx;
        float gy = -0.5f + 0.25f * ky;
        float px = (bx + bw * gx) * (float)WDIM - 0.5f;
        float py = (by + bh * gy) * (float)HDIM - 0.5f;
        float x0 = floorf(px), y0 = floorf(py);
        float a  = aw[k];
#pragma unroll
        for (int dx = 0; dx < 2; dx++) {
#pragma unroll
            for (int dy = 0; dy < 2; dy++) {
                float xi = x0 + dx, yi = y0 + dy;
                if (xi < 0.f || xi >= (float)WDIM || yi < 0.f || yi >= (float)HDIM) continue;
                float w = (1.f - fabsf(px - xi)) * (1.f - fabsf(py - yi));
                int idx = (int)yi * WDIM + (int)xi;
                acc = fmaf(a * w, vbase[(size_t)idx * D], acc);
            }
        }
    }
    OUT[(size_t)l * D + h * HD + lane] = acc;
}

// ------------------------- fused residual + LayerNorm ---------------------
__global__ void ln_residual_kernel(const float* __restrict__ Xin,
                                   const float* __restrict__ Add,
                                   const float* __restrict__ gamma,
                                   const float* __restrict__ beta,
                                   float* __restrict__ Out) {
    int row  = blockIdx.x * (blockDim.x >> 5) + (threadIdx.x >> 5);
    int lane = threadIdx.x & 31;
    if (row >= L) return;
    const float* xr = Xin + (size_t)row * D;
    const float* ar = Add + (size_t)row * D;
    float v[D / 32];
    float s = 0.f;
#pragma unroll
    for (int i = 0; i < D / 32; i++) {
        int c = lane + 32 * i;
        v[i] = xr[c] + ar[c];
        s += v[i];
    }
#pragma unroll
    for (int o = 16; o; o >>= 1) s += __shfl_xor_sync(0xFFFFFFFFu, s, o);
    float m = s * (1.f / D);
    float vs = 0.f;
#pragma unroll
    for (int i = 0; i < D / 32; i++) {
        float d = v[i] - m;
        vs += d * d;
    }
#pragma unroll
    for (int o = 16; o; o >>= 1) vs += __shfl_xor_sync(0xFFFFFFFFu, vs, o);
    float rstd = rsqrtf(vs * (1.f / D) + EPS);
    float* orow = Out + (size_t)row * D;
#pragma unroll
    for (int i = 0; i < D / 32; i++) {
        int c = lane + 32 * i;
        orow[c] = (v[i] - m) * rstd * gamma[c] + beta[c];
    }
}

// ------------------------- host-side launchers -----------------------------
template <int EPI>
static void launch_mma_gemm(const float* A, const float* B, const float* bias,
                            float* C, int M, int N, int K) {
    cudaFuncSetAttribute(mma_gemm_kernel<EPI>,
                         cudaFuncAttributeMaxDynamicSharedMemorySize, SMEM_BYTES);
    dim3 grid((N + BN - 1) / BN, M / BM);
    mma_gemm_kernel<EPI><<<grid, 256, SMEM_BYTES>>>(A, B, bias, C, M, N, K);
}

extern "C" void kernel_launch(void* const* d_in, const int* in_sizes, int n_in,
                              void* d_out, int out_size) {
    const float* src   = (const float*)d_in[0];
    const float* pos   = (const float*)d_in[1];
    const float* Wv    = (const float*)d_in[2];
    const float* bv    = (const float*)d_in[3];
    const float* Wbox  = (const float*)d_in[4];
    const float* bbox  = (const float*)d_in[5];
    const float* Wattn = (const float*)d_in[6];
    const float* battn = (const float*)d_in[7];
    const float* Wo    = (const float*)d_in[8];
    const float* bo    = (const float*)d_in[9];
    const float* W1    = (const float*)d_in[10];
    const float* b1    = (const float*)d_in[11];
    const float* W2    = (const float*)d_in[12];
    const float* b2    = (const float*)d_in[13];
    const float* ln1_g = (const float*)d_in[14];
    const float* ln1_b = (const float*)d_in[15];
    const float* ln2_g = (const float*)d_in[16];
    const float* ln2_b = (const float*)d_in[17];

    float *X, *P, *Q, *VAL, *OUT, *TMP, *FF, *AW, *OFF;
    cudaGetSymbolAddress((void**)&X,   g_X);
    cudaGetSymbolAddress((void**)&P,   g_P);
    cudaGetSymbolAddress((void**)&Q,   g_Q);
    cudaGetSymbolAddress((void**)&VAL, g_VAL);
    cudaGetSymbolAddress((void**)&OUT, g_OUT);
    cudaGetSymbolAddress((void**)&TMP, g_TMP);
    cudaGetSymbolAddress((void**)&FF,  g_FF);
    cudaGetSymbolAddress((void**)&AW,  g_AW);
    cudaGetSymbolAddress((void**)&OFF, g_OFF);

    {
        dim3 tb(32, 8);
        dim3 tg(L / 32, D / 32);
        transpose_kernel<<<tg, tb>>>(src, X);
        transpose_kernel<<<tg, tb>>>(pos, P);
    }

    for (int i = 0; i < 2; i++) {
        const float* Wv_i    = Wv    + (size_t)i * D * D;
        const float* bv_i    = bv    + (size_t)i * D;
        const float* Wbox_i  = Wbox  + (size_t)i * D * (NH * 4);
        const float* bbox_i  = bbox  + (size_t)i * (NH * 4);
        const float* Wattn_i = Wattn + (size_t)i * D * (NH * K2);
        const float* battn_i = battn + (size_t)i * (NH * K2);
        const float* Wo_i    = Wo    + (size_t)i * D * D;
        const float* bo_i    = bo    + (size_t)i * D;
        const float* W1_i    = W1    + (size_t)i * D * DFF;
        const float* b1_i    = b1    + (size_t)i * DFF;
        const float* W2_i    = W2    + (size_t)i * DFF * D;
        const float* b2_i    = b2    + (size_t)i * D;
        const float* ln1g_i  = ln1_g + (size_t)i * D;
        const float* ln1b_i  = ln1_b + (size_t)i * D;
        const float* ln2g_i  = ln2_g + (size_t)i * D;
        const float* ln2b_i  = ln2_b + (size_t)i * D;

        add_kernel<<<(L * D + 255) / 256, 256>>>(X, P, Q, L * D);

        launch_mma_gemm<1>(X, Wv_i, bv_i, VAL, L, D, D);
        launch_mma_gemm<1>(Q, Wattn_i, battn_i, AW, L, NH * K2, D);
        softmax25_kernel<<<(L * NH + 255) / 256, 256>>>(AW);
        launch_mma_gemm<1>(Q, Wbox_i, bbox_i, OFF, L, NH * 4, D);

        box_sample_kernel<<<L, NH * 32>>>(VAL, AW, OFF, OUT);

        launch_mma_gemm<1>(OUT, Wo_i, bo_i, TMP, L, D, D);
        ln_residual_kernel<<<L / 8, 256>>>(X, TMP, ln1g_i, ln1b_i, X);

        launch_mma_gemm<2>(X, W1_i, b1_i, FF, L, DFF, D);
        launch_mma_gemm<1>(FF, W2_i, b2_i, TMP, L, D, DFF);
        float* lnout = (i == 1) ? (float*)d_out : X;
        ln_residual_kernel<<<L / 8, 256>>>(X, TMP, ln2g_i, ln2b_i, lnout);
    }
}